// round 12
// baseline (speedup 1.0000x reference)
#include <cuda_runtime.h>
#include <cuda_bf16.h>
#include <math.h>
#include <stdint.h>

#define Bv  2
#define Sv  2048
#define Dv  2048
#define Hv  16
#define DKv 128
#define Mv  (Bv*Sv)   // 4096

// Scratch (allocation-free rule: __device__ globals)
__device__ __nv_bfloat16 g_xh[(size_t)Mv*Dv];              // x hi
__device__ __nv_bfloat16 g_xl[(size_t)Mv*Dv];              // x lo
__device__ __nv_bfloat16 g_wh[(size_t)4*Dv*Dv];            // Wq|Wk|Wv|Wo hi
__device__ __nv_bfloat16 g_wl[(size_t)4*Dv*Dv];            // Wq|Wk|Wv|Wo lo
__device__ __nv_bfloat16 g_qh[(size_t)Mv*Dv];              // Q (rope, scaled) hi
__device__ __nv_bfloat16 g_ql[(size_t)Mv*Dv];              // Q lo
__device__ __nv_bfloat16 g_kh[(size_t)Mv*Dv];              // K (rope) hi
__device__ __nv_bfloat16 g_kl[(size_t)Mv*Dv];              // K lo
__device__ __nv_bfloat16 g_vh[(size_t)Mv*Dv];              // V hi
__device__ __nv_bfloat16 g_vl[(size_t)Mv*Dv];              // V lo
__device__ __nv_bfloat16 g_ch[(size_t)Mv*Dv];              // ctx hi
__device__ __nv_bfloat16 g_cl[(size_t)Mv*Dv];              // ctx lo

// ---------------------------------------------------------------------------
// helpers
// ---------------------------------------------------------------------------
__device__ __forceinline__ uint32_t smem_u32(const void* p){
    uint32_t a;
    asm("{ .reg .u64 t; cvta.to.shared.u64 t, %1; cvt.u32.u64 %0, t; }" : "=r"(a) : "l"(p));
    return a;
}
__device__ __forceinline__ uint32_t pack_bf2(float x, float y){
    __nv_bfloat162 h = __floats2bfloat162_rn(x, y);
    return *reinterpret_cast<uint32_t*>(&h);
}
__device__ __forceinline__ void ldsm4(uint32_t addr, uint32_t r[4]){
    asm volatile("ldmatrix.sync.aligned.m8n8.x4.shared.b16 {%0,%1,%2,%3}, [%4];"
                 : "=r"(r[0]), "=r"(r[1]), "=r"(r[2]), "=r"(r[3]) : "r"(addr));
}
__device__ __forceinline__ void ldsm4t(uint32_t addr, uint32_t r[4]){
    asm volatile("ldmatrix.sync.aligned.m8n8.x4.trans.shared.b16 {%0,%1,%2,%3}, [%4];"
                 : "=r"(r[0]), "=r"(r[1]), "=r"(r[2]), "=r"(r[3]) : "r"(addr));
}
__device__ __forceinline__ void mma16816(float c[4], const uint32_t a[4], const uint32_t b[2]){
    asm volatile(
        "mma.sync.aligned.m16n8k16.row.col.f32.bf16.bf16.f32 "
        "{%0,%1,%2,%3}, {%4,%5,%6,%7}, {%8,%9}, {%0,%1,%2,%3};"
        : "+f"(c[0]), "+f"(c[1]), "+f"(c[2]), "+f"(c[3])
        : "r"(a[0]), "r"(a[1]), "r"(a[2]), "r"(a[3]), "r"(b[0]), "r"(b[1]));
}
__device__ __forceinline__ void split2(float x, float y, uint32_t& hi, uint32_t& lo){
    float hx = __bfloat162float(__float2bfloat16(x));
    float hy = __bfloat162float(__float2bfloat16(y));
    hi = pack_bf2(hx, hy);
    lo = pack_bf2(x - hx, y - hy);
}
__device__ __forceinline__ void cp16(uint32_t dst, const void* src){
    asm volatile("cp.async.cg.shared.global [%0], [%1], 16;" :: "r"(dst), "l"(src));
}
__device__ __forceinline__ void cp_commit(){
    asm volatile("cp.async.commit_group;" ::: "memory");
}
template<int N>
__device__ __forceinline__ void cp_wait(){
    asm volatile("cp.async.wait_group %0;" :: "n"(N) : "memory");
}

// ---------------------------------------------------------------------------
// fp32 -> bf16 hi/lo planes
// ---------------------------------------------------------------------------
__global__ __launch_bounds__(256)
void split_x(const float* __restrict__ src, __nv_bfloat16* __restrict__ hi,
             __nv_bfloat16* __restrict__ lo, int n8)
{
    const int i = blockIdx.x * blockDim.x + threadIdx.x;
    if (i >= n8) return;
    const float4* s = (const float4*)src + 2*(size_t)i;
    float4 v0 = s[0], v1 = s[1];
    uint32_t h[4], l[4];
    split2(v0.x, v0.y, h[0], l[0]); split2(v0.z, v0.w, h[1], l[1]);
    split2(v1.x, v1.y, h[2], l[2]); split2(v1.z, v1.w, h[3], l[3]);
    ((uint4*)hi)[i] = make_uint4(h[0], h[1], h[2], h[3]);
    ((uint4*)lo)[i] = make_uint4(l[0], l[1], l[2], l[3]);
}

// all 4 weights in one launch (dst planes are contiguous)
__global__ __launch_bounds__(256)
void split_w4(const float* __restrict__ s0, const float* __restrict__ s1,
              const float* __restrict__ s2, const float* __restrict__ s3,
              __nv_bfloat16* __restrict__ hi, __nv_bfloat16* __restrict__ lo)
{
    const size_t i = (size_t)blockIdx.x * blockDim.x + threadIdx.x;  // < 4*WN/8
    const int sel = (int)(i >> 19);                  // WN/8 = 524288 per weight
    const size_t local = i & 524287u;
    const float* src = (sel == 0) ? s0 : (sel == 1) ? s1 : (sel == 2) ? s2 : s3;
    const float4* s = (const float4*)src + 2*local;
    float4 v0 = s[0], v1 = s[1];
    uint32_t h[4], l[4];
    split2(v0.x, v0.y, h[0], l[0]); split2(v0.z, v0.w, h[1], l[1]);
    split2(v1.x, v1.y, h[2], l[2]); split2(v1.z, v1.w, h[3], l[3]);
    ((uint4*)hi)[i] = make_uint4(h[0], h[1], h[2], h[3]);
    ((uint4*)lo)[i] = make_uint4(l[0], l[1], l[2], l[3]);
}

// ---------------------------------------------------------------------------
// Pipelined bf16 GEMM mainloop (3-term hi/lo).
// 128x128 tile, BK=64, 256 threads (8 warps 2x4), 3-stage cp.async ring,
// ONE __syncthreads per chunk (stage for c+2 was last read at c-1).
// ---------------------------------------------------------------------------
#define SA      72                  // bf16 cols per row incl pad (144B rows)
#define TILE_B  (128*SA*2)          // 18432 B
#define STG_B   (4*TILE_B)          // 73728 B
#define GSM_TOTAL (3*STG_B)         // 221184 B
#define NCH     (Dv/64)             // 32

struct GemmCore {
    float acc[4][4][4];
    int wm, wn, lane;

    __device__ __forceinline__ void run(char* smem,
        const __nv_bfloat16* Ah, const __nv_bfloat16* Al,
        const __nv_bfloat16* Bh, const __nv_bfloat16* Bl,
        int row0, int col0, int tid)
    {
        lane = tid & 31;
        const int wid = tid >> 5;
        wm = wid >> 2;
        wn = wid & 3;
        #pragma unroll
        for (int i = 0; i < 4; i++)
            #pragma unroll
            for (int j = 0; j < 4; j++)
                #pragma unroll
                for (int q = 0; q < 4; q++) acc[i][j][q] = 0.0f;

        const int la_r = (lane & 7) + ((lane >> 3) & 1) * 8;
        const int la_k = (lane >> 4) * 8;
        const int lb_c = (lane & 7) + (lane >> 4) * 8;
        const int lb_k = ((lane >> 3) & 1) * 8;

        const int lrow  = tid >> 1;
        const int lhalf = tid & 1;
        const __nv_bfloat16* aHg = Ah + (size_t)(row0 + lrow) * Dv + lhalf*32;
        const __nv_bfloat16* aLg = Al + (size_t)(row0 + lrow) * Dv + lhalf*32;
        const __nv_bfloat16* bHg = Bh + (size_t)(col0 + lrow) * Dv + lhalf*32;
        const __nv_bfloat16* bLg = Bl + (size_t)(col0 + lrow) * Dv + lhalf*32;
        const uint32_t dsto = (uint32_t)(lrow*(SA*2) + lhalf*64);
        const uint32_t sb = smem_u32(smem);

        // prologue: chunks 0,1 into stages 0,1
        #pragma unroll
        for (int s = 0; s < 2; s++) {
            const uint32_t dst = sb + s*STG_B + dsto;
            const size_t go = (size_t)s * 64;
            #pragma unroll
            for (int u = 0; u < 4; u++) {
                cp16(dst            + u*16, aHg + go + u*8);
                cp16(dst +   TILE_B + u*16, aLg + go + u*8);
                cp16(dst + 2*TILE_B + u*16, bHg + go + u*8);
                cp16(dst + 3*TILE_B + u*16, bLg + go + u*8);
            }
            cp_commit();
        }

        int stage = 0;
        for (int c = 0; c < NCH; c++) {
            cp_wait<1>();
            __syncthreads();

            const uint32_t cur = sb + stage * STG_B;
            #pragma unroll
            for (int ks = 0; ks < 4; ks++) {
                uint32_t ah[4][4], al[4][4], bh[4][2], bl[4][2];
                #pragma unroll
                for (int mi = 0; mi < 4; mi++) {
                    const uint32_t off = (uint32_t)(((wm*64 + mi*16 + la_r)*SA + ks*16 + la_k) * 2);
                    ldsm4(cur + off,          ah[mi]);
                    ldsm4(cur + TILE_B + off, al[mi]);
                }
                #pragma unroll
                for (int p = 0; p < 2; p++) {
                    const uint32_t off = (uint32_t)(((wn*32 + p*16 + lb_c)*SA + ks*16 + lb_k) * 2);
                    uint32_t t[4];
                    ldsm4(cur + 2*TILE_B + off, t);
                    bh[2*p][0] = t[0]; bh[2*p][1] = t[1];
                    bh[2*p+1][0] = t[2]; bh[2*p+1][1] = t[3];
                    ldsm4(cur + 3*TILE_B + off, t);
                    bl[2*p][0] = t[0]; bl[2*p][1] = t[1];
                    bl[2*p+1][0] = t[2]; bl[2*p+1][1] = t[3];
                }
                #pragma unroll
                for (int mi = 0; mi < 4; mi++)
                    #pragma unroll
                    for (int ni = 0; ni < 4; ni++) {
                        mma16816(acc[mi][ni], ah[mi], bh[ni]);
                        mma16816(acc[mi][ni], al[mi], bh[ni]);
                        mma16816(acc[mi][ni], ah[mi], bl[ni]);
                    }
            }

            // issue chunk c+2 into stage (c+2)%3 (last read at c-1; safe after barrier)
            if (c + 2 < NCH) {
                int nst = stage + 2; if (nst >= 3) nst -= 3;
                const uint32_t dst = sb + nst*STG_B + dsto;
                const size_t go = (size_t)(c+2) * 64;
                #pragma unroll
                for (int u = 0; u < 4; u++) {
                    cp16(dst            + u*16, aHg + go + u*8);
                    cp16(dst +   TILE_B + u*16, aLg + go + u*8);
                    cp16(dst + 2*TILE_B + u*16, bHg + go + u*8);
                    cp16(dst + 3*TILE_B + u*16, bLg + go + u*8);
                }
            }
            cp_commit();   // unconditional: keeps group numbering exact
            if (++stage == 3) stage = 0;
        }
    }
};

// Merged Q/K/V projection GEMM: blockIdx.z = 0(Q) / 1(K) / 2(V)
__global__ __launch_bounds__(256, 1)
void gemm_qkv(const __nv_bfloat16* __restrict__ xh, const __nv_bfloat16* __restrict__ xl,
              const __nv_bfloat16* __restrict__ wh, const __nv_bfloat16* __restrict__ wl,
              const float* __restrict__ fc, const float* __restrict__ fs,
              float* __restrict__ outK, float* __restrict__ outV,
              __nv_bfloat16* __restrict__ qh, __nv_bfloat16* __restrict__ ql,
              __nv_bfloat16* __restrict__ kh, __nv_bfloat16* __restrict__ kl,
              __nv_bfloat16* __restrict__ vh, __nv_bfloat16* __restrict__ vl)
{
    extern __shared__ __align__(1024) char smem[];
    const int z    = blockIdx.z;
    const int row0 = blockIdx.y * 128;
    const int col0 = blockIdx.x * 128;
    const size_t WN = (size_t)Dv*Dv;

    GemmCore core;
    core.run(smem, xh, xl, wh + (size_t)z*WN, wl + (size_t)z*WN, row0, col0, threadIdx.x);

    float* Cf = (z == 1) ? outK : (z == 2) ? outV : nullptr;
    __nv_bfloat16* Ph = (z == 0) ? qh : (z == 1) ? kh : vh;
    __nv_bfloat16* Pl = (z == 0) ? ql : (z == 1) ? kl : vl;
    const bool ROPE = (z <= 1);
    const int lane = core.lane;

    #pragma unroll
    for (int mi = 0; mi < 4; mi++) {
        const int gr0 = row0 + core.wm*64 + mi*16 + (lane >> 2);
        const int gr1 = gr0 + 8;
        #pragma unroll
        for (int ni = 0; ni < 4; ni++) {
            const int gc = col0 + core.wn*32 + ni*8 + (lane & 3)*2;
            float c0 = core.acc[mi][ni][0], c1 = core.acc[mi][ni][1];
            float c2 = core.acc[mi][ni][2], c3 = core.acc[mi][ni][3];
            if (ROPE) {
                const int ip = (gc & (DKv - 1)) >> 1;
                const int s0 = gr0 & (Sv - 1), s1 = gr1 & (Sv - 1);
                float ca = fc[s0*64 + ip], sa = fs[s0*64 + ip];
                float cb = fc[s1*64 + ip], sb2 = fs[s1*64 + ip];
                float t0 = c0*ca - c1*sa, t1 = c0*sa + c1*ca;
                float t2 = c2*cb - c3*sb2, t3 = c2*sb2 + c3*cb;
                c0 = t0; c1 = t1; c2 = t2; c3 = t3;
            }
            if (z == 0) {
                const float s = 0.08838834764831845f;   // 1/sqrt(128)
                c0 *= s; c1 *= s; c2 *= s; c3 *= s;
            } else {
                float2 r0; r0.x = c0; r0.y = c1;
                float2 r1; r1.x = c2; r1.y = c3;
                *(float2*)(Cf + (size_t)gr0 * Dv + gc) = r0;
                *(float2*)(Cf + (size_t)gr1 * Dv + gc) = r1;
            }
            uint32_t h0, l0, h1, l1;
            split2(c0, c1, h0, l0);
            split2(c2, c3, h1, l1);
            *(uint32_t*)(Ph + (size_t)gr0 * Dv + gc) = h0;
            *(uint32_t*)(Pl + (size_t)gr0 * Dv + gc) = l0;
            *(uint32_t*)(Ph + (size_t)gr1 * Dv + gc) = h1;
            *(uint32_t*)(Pl + (size_t)gr1 * Dv + gc) = l1;
        }
    }
}

// Wo GEMM: fp32 out only
__global__ __launch_bounds__(256, 1)
void gemm_wo(const __nv_bfloat16* __restrict__ Ah, const __nv_bfloat16* __restrict__ Al,
             const __nv_bfloat16* __restrict__ Bh, const __nv_bfloat16* __restrict__ Bl,
             float* __restrict__ C)
{
    extern __shared__ __align__(1024) char smem[];
    const int row0 = blockIdx.y * 128;
    const int col0 = blockIdx.x * 128;

    GemmCore core;
    core.run(smem, Ah, Al, Bh, Bl, row0, col0, threadIdx.x);

    const int lane = core.lane;
    #pragma unroll
    for (int mi = 0; mi < 4; mi++) {
        const int gr0 = row0 + core.wm*64 + mi*16 + (lane >> 2);
        const int gr1 = gr0 + 8;
        #pragma unroll
        for (int ni = 0; ni < 4; ni++) {
            const int gc = col0 + core.wn*32 + ni*8 + (lane & 3)*2;
            float2 r0; r0.x = core.acc[mi][ni][0]; r0.y = core.acc[mi][ni][1];
            float2 r1; r1.x = core.acc[mi][ni][2]; r1.y = core.acc[mi][ni][3];
            *(float2*)(C + (size_t)gr0 * Dv + gc) = r0;
            *(float2*)(C + (size_t)gr1 * Dv + gc) = r1;
        }
    }
}

// ---------------------------------------------------------------------------
// Tensor-core flash attention. BM=128 q-rows/CTA, 256 threads (8 warps x 16
// rows). Q lives in REGISTERS (loaded once); smem is a 2-stage K/V ring.
// 2 syncs per kv tile; heavy q-tiles launched first.
// SMEM: 2 x (Kh|Kl|Vh|Vl)[64][136] = 139264 B.
// ---------------------------------------------------------------------------
#define SPa     136
#define KT_B    (64*SPa*2)        // 17408 B
#define AST_B   (4*KT_B)          // 69632 B per stage
#define ASM_TOT (2*AST_B)         // 139264 B

__global__ __launch_bounds__(256, 1)
void attn_mma(const __nv_bfloat16* __restrict__ Qh, const __nv_bfloat16* __restrict__ Ql,
              const __nv_bfloat16* __restrict__ Kh, const __nv_bfloat16* __restrict__ Kl,
              const __nv_bfloat16* __restrict__ Vh, const __nv_bfloat16* __restrict__ Vl,
              __nv_bfloat16* __restrict__ ch, __nv_bfloat16* __restrict__ cl)
{
    extern __shared__ __align__(16) char smem[];
    const uint32_t sb = smem_u32(smem);
    const int tid  = threadIdx.x;
    const int lane = tid & 31;
    const int warp = tid >> 5;           // 0..7
    const int qt   = (int)(gridDim.x - 1 - blockIdx.x);   // heavy tiles first
    const int q0   = qt * 128;
    const int h    = blockIdx.y;
    const int b    = blockIdx.z;
    const size_t hoff = (size_t)h * DKv;

    // ---- stage Q through smem once, keep in registers ----
    {
        const int lrq = tid >> 1;
        const int lcq = (tid & 1) * 64;
        const uint32_t drq = (uint32_t)(lrq*SPa + lcq) * 2;
        const size_t qoff = (size_t)(b*Sv + q0 + lrq) * Dv + hoff + lcq;
        #pragma unroll
        for (int u = 0; u < 8; u++) {
            cp16(sb +          drq + u*16, Qh + qoff + u*8);
            cp16(sb + 2*KT_B + drq + u*16, Ql + qoff + u*8);
        }
    }
    cp_commit();
    cp_wait<0>();
    __syncthreads();

    uint32_t qfh[8][4], qfl[8][4];
    #pragma unroll
    for (int ks = 0; ks < 8; ks++) {
        const uint32_t qaddr = sb +
            (uint32_t)(((warp*16 + (lane & 15))*SPa + ks*16 + (lane >> 4)*8) * 2);
        ldsm4(qaddr,          qfh[ks]);
        ldsm4(qaddr + 2*KT_B, qfl[ks]);
    }
    __syncthreads();   // all warps done reading Q staging before KV overwrites

    // K/V loader addressing: 256 threads -> 64 rows x 4 quarters
    const int lrk = tid >> 2;
    const int lck = (tid & 3) * 32;
    const uint32_t drk = (uint32_t)(lrk*SPa + lck) * 2;
    const size_t koff0 = (size_t)(b*Sv + lrk) * Dv + hoff + lck;   // + kt*64*Dv

    const int ktmax = 2*qt + 1;

    // prologue: tiles 0 and 1 into stages 0 and 1 (ktmax >= 1 always)
    #pragma unroll
    for (int s = 0; s < 2; s++) {
        const uint32_t base = sb + s*AST_B;
        const size_t go = koff0 + (size_t)s*64*Dv;
        #pragma unroll
        for (int u = 0; u < 4; u++) {
            cp16(base +          drk + u*16, Kh + go + u*8);
            cp16(base +   KT_B + drk + u*16, Kl + go + u*8);
            cp16(base + 2*KT_B + drk + u*16, Vh + go + u*8);
            cp16(base + 3*KT_B + drk + u*16, Vl + go + u*8);
        }
        cp_commit();
    }

    float ctxa[16][4];
    #pragma unroll
    for (int i = 0; i < 16; i++)
        #pragma unroll
        for (int j = 0; j < 4; j++) ctxa[i][j] = 0.0f;
    float m0 = -1e30f, m1 = -1e30f, l0 = 0.0f, l1 = 0.0f;

    for (int kt = 0; kt <= ktmax; kt++) {
        cp_wait<1>();        // tile kt resident
        __syncthreads();
        const uint32_t KB = sb + (kt & 1) * AST_B;
        const uint32_t VB = KB + 2*KT_B;

        // ---- scores: S[16 x 64] per warp over dk=128, hi/lo 3-term ----
        float sc[8][4];
        #pragma unroll
        for (int nt = 0; nt < 8; nt++)
            #pragma unroll
            for (int j = 0; j < 4; j++) sc[nt][j] = 0.0f;

        #pragma unroll
        for (int ks = 0; ks < 8; ks++) {
            #pragma unroll
            for (int p = 0; p < 4; p++) {
                const uint32_t kaddr = KB +
                    (uint32_t)(((p*16 + (lane & 15))*SPa + ks*16 + (lane >> 4)*8) * 2);
                uint32_t th[4], tl[4];
                ldsm4(kaddr,        th);
                ldsm4(kaddr + KT_B, tl);
                uint32_t bh0[2] = {th[0], th[2]}, bh1[2] = {th[1], th[3]};
                uint32_t bl0[2] = {tl[0], tl[2]}, bl1[2] = {tl[1], tl[3]};
                mma16816(sc[2*p],   qfh[ks], bh0);
                mma16816(sc[2*p],   qfl[ks], bh0);
                mma16816(sc[2*p],   qfh[ks], bl0);
                mma16816(sc[2*p+1], qfh[ks], bh1);
                mma16816(sc[2*p+1], qfl[ks], bh1);
                mma16816(sc[2*p+1], qfh[ks], bl1);
            }
        }

        // ---- softmax ----
        const int gr0 = q0 + warp*16 + (lane >> 2);
        const int gr1 = gr0 + 8;
        if (kt >= 2*qt) {    // only the last two tiles can cross the diagonal
            #pragma unroll
            for (int nt = 0; nt < 8; nt++) {
                const int cb = kt*64 + nt*8 + (lane & 3)*2;
                if (cb     > gr0) sc[nt][0] = -1e30f;
                if (cb + 1 > gr0) sc[nt][1] = -1e30f;
                if (cb     > gr1) sc[nt][2] = -1e30f;
                if (cb + 1 > gr1) sc[nt][3] = -1e30f;
            }
        }
        float mx0 = -1e30f, mx1 = -1e30f;
        #pragma unroll
        for (int nt = 0; nt < 8; nt++) {
            mx0 = fmaxf(mx0, fmaxf(sc[nt][0], sc[nt][1]));
            mx1 = fmaxf(mx1, fmaxf(sc[nt][2], sc[nt][3]));
        }
        mx0 = fmaxf(mx0, __shfl_xor_sync(0xffffffffu, mx0, 1));
        mx0 = fmaxf(mx0, __shfl_xor_sync(0xffffffffu, mx0, 2));
        mx1 = fmaxf(mx1, __shfl_xor_sync(0xffffffffu, mx1, 1));
        mx1 = fmaxf(mx1, __shfl_xor_sync(0xffffffffu, mx1, 2));

        const float mn0 = fmaxf(m0, mx0), mn1 = fmaxf(m1, mx1);
        const float a0 = __expf(m0 - mn0), a1 = __expf(m1 - mn1);
        m0 = mn0; m1 = mn1;

        float s0 = 0.0f, s1 = 0.0f;
        #pragma unroll
        for (int nt = 0; nt < 8; nt++) {
            sc[nt][0] = __expf(sc[nt][0] - mn0);
            sc[nt][1] = __expf(sc[nt][1] - mn0);
            sc[nt][2] = __expf(sc[nt][2] - mn1);
            sc[nt][3] = __expf(sc[nt][3] - mn1);
            s0 += sc[nt][0] + sc[nt][1];
            s1 += sc[nt][2] + sc[nt][3];
        }
        s0 += __shfl_xor_sync(0xffffffffu, s0, 1);
        s0 += __shfl_xor_sync(0xffffffffu, s0, 2);
        s1 += __shfl_xor_sync(0xffffffffu, s1, 1);
        s1 += __shfl_xor_sync(0xffffffffu, s1, 2);
        l0 = l0 * a0 + s0;
        l1 = l1 * a1 + s1;

        #pragma unroll
        for (int nt = 0; nt < 16; nt++) {
            ctxa[nt][0] *= a0; ctxa[nt][1] *= a0;
            ctxa[nt][2] *= a1; ctxa[nt][3] *= a1;
        }

        // pack P (C-frag -> A-frag), hi/lo
        uint32_t pah[4][4], pal[4][4];
        #pragma unroll
        for (int k2 = 0; k2 < 4; k2++) {
            split2(sc[2*k2][0],   sc[2*k2][1],   pah[k2][0], pal[k2][0]);
            split2(sc[2*k2][2],   sc[2*k2][3],   pah[k2][1], pal[k2][1]);
            split2(sc[2*k2+1][0], sc[2*k2+1][1], pah[k2][2], pal[k2][2]);
            split2(sc[2*k2+1][2], sc[2*k2+1][3], pah[k2][3], pal[k2][3]);
        }

        // ---- ctx += P @ V  (V via ldmatrix.trans) ----
        #pragma unroll
        for (int k2 = 0; k2 < 4; k2++) {
            #pragma unroll
            for (int p = 0; p < 8; p++) {
                const uint32_t vaddr = VB +
                    (uint32_t)(((k2*16 + (lane & 15))*SPa + p*16 + (lane >> 4)*8) * 2);
                uint32_t vh[4], vl[4];
                ldsm4t(vaddr,        vh);
                ldsm4t(vaddr + KT_B, vl);
                uint32_t bh0[2] = {vh[0], vh[1]}, bh1[2] = {vh[2], vh[3]};
                uint32_t bl0[2] = {vl[0], vl[1]}, bl1[2] = {vl[2], vl[3]};
                mma16816(ctxa[2*p],   pah[k2], bh0);
                mma16816(ctxa[2*p],   pal[k2], bh0);
                mma16816(ctxa[2*p],   pah[k2], bl0);
                mma16816(ctxa[2*p+1], pah[k2], bh1);
                mma16816(ctxa[2*p+1], pal[k2], bh1);
                mma16816(ctxa[2*p+1], pah[k2], bl1);
            }
        }

        // all warps done with stage (kt&1) -> refill it with tile kt+2
        __syncthreads();
        if (kt + 2 <= ktmax) {
            const uint32_t base = sb + (kt & 1) * AST_B;
            const size_t go = koff0 + (size_t)(kt+2)*64*Dv;
            #pragma unroll
            for (int u = 0; u < 4; u++) {
                cp16(base +          drk + u*16, Kh + go + u*8);
                cp16(base +   KT_B + drk + u*16, Kl + go + u*8);
                cp16(base + 2*KT_B + drk + u*16, Vh + go + u*8);
                cp16(base + 3*KT_B + drk + u*16, Vl + go + u*8);
            }
        }
        cp_commit();   // unconditional: keeps group numbering exact
    }

    // epilogue: ctx/l -> bf16 hi/lo planes
    const float i0 = 1.0f / l0, i1 = 1.0f / l1;
    const size_t r0g = (size_t)(b*Sv + q0 + warp*16 + (lane >> 2));
    const size_t r1g = r0g + 8;
    #pragma unroll
    for (int nt = 0; nt < 16; nt++) {
        const size_t col = hoff + nt*8 + (lane & 3)*2;
        uint32_t h0, l0u, h1, l1u;
        split2(ctxa[nt][0]*i0, ctxa[nt][1]*i0, h0, l0u);
        split2(ctxa[nt][2]*i1, ctxa[nt][3]*i1, h1, l1u);
        *(uint32_t*)(ch + r0g*Dv + col) = h0;
        *(uint32_t*)(cl + r0g*Dv + col) = l0u;
        *(uint32_t*)(ch + r1g*Dv + col) = h1;
        *(uint32_t*)(cl + r1g*Dv + col) = l1u;
    }
}

// ---------------------------------------------------------------------------
extern "C" void kernel_launch(void* const* d_in, const int* in_sizes, int n_in,
                              void* d_out, int out_size)
{
    const float* x  = (const float*)d_in[0];
    const float* fc = (const float*)d_in[1];
    const float* fs = (const float*)d_in[2];
    // d_in[3] = mask (unused: -1e9 mask == strict causal in f32)
    const float* Wq = (const float*)d_in[4];
    const float* Wk = (const float*)d_in[5];
    const float* Wv = (const float*)d_in[6];
    const float* Wo = (const float*)d_in[7];

    float* out  = (float*)d_out;
    float* outK = out  + (size_t)Mv*Dv;
    float* outV = outK + (size_t)Mv*Dv;

    __nv_bfloat16 *xh, *xl, *wh, *wl, *qh, *ql, *kh, *kl, *vh, *vl, *ch, *cl;
    cudaGetSymbolAddress((void**)&xh, g_xh);
    cudaGetSymbolAddress((void**)&xl, g_xl);
    cudaGetSymbolAddress((void**)&wh, g_wh);
    cudaGetSymbolAddress((void**)&wl, g_wl);
    cudaGetSymbolAddress((void**)&qh, g_qh);
    cudaGetSymbolAddress((void**)&ql, g_ql);
    cudaGetSymbolAddress((void**)&kh, g_kh);
    cudaGetSymbolAddress((void**)&kl, g_kl);
    cudaGetSymbolAddress((void**)&vh, g_vh);
    cudaGetSymbolAddress((void**)&vl, g_vl);
    cudaGetSymbolAddress((void**)&ch, g_ch);
    cudaGetSymbolAddress((void**)&cl, g_cl);

    cudaFuncSetAttribute(gemm_qkv, cudaFuncAttributeMaxDynamicSharedMemorySize, GSM_TOTAL);
    cudaFuncSetAttribute(gemm_wo,  cudaFuncAttributeMaxDynamicSharedMemorySize, GSM_TOTAL);
    cudaFuncSetAttribute(attn_mma, cudaFuncAttributeMaxDynamicSharedMemorySize, ASM_TOT);

    const size_t WN = (size_t)Dv*Dv;     // 4M elems per weight

    split_x<<<(Mv*Dv/8 + 255)/256, 256>>>(x, xh, xl, Mv*Dv/8);
    split_w4<<<(int)(4*WN/8/256), 256>>>(Wq, Wk, Wv, Wo, wh, wl);

    dim3 ggrid(Dv/128, Mv/128, 3);   // (16, 32, 3)
    gemm_qkv<<<ggrid, 256, GSM_TOTAL>>>(xh, xl, wh, wl, fc, fs, outK, outV,
                                        qh, ql, kh, kl, vh, vl);

    attn_mma<<<dim3(Sv/128, Hv, Bv), 256, ASM_TOT>>>(qh, ql, kh, kl, vh, vl, ch, cl);

    gemm_wo<<<dim3(Dv/128, Mv/128), 256, GSM_TOTAL>>>(ch, cl, wh + 3*WN, wl + 3*WN, out);
}

// round 15
// speedup vs baseline: 1.0112x; 1.0112x over previous
#include <cuda_runtime.h>
#include <cuda_bf16.h>
#include <math.h>
#include <stdint.h>

#define Bv  2
#define Sv  2048
#define Dv  2048
#define Hv  16
#define DKv 128
#define Mv  (Bv*Sv)   // 4096

// Scratch (allocation-free rule: __device__ globals)
__device__ __nv_bfloat16 g_xh[(size_t)Mv*Dv];              // x hi
__device__ __nv_bfloat16 g_xl[(size_t)Mv*Dv];              // x lo
__device__ __nv_bfloat16 g_wh[(size_t)4*Dv*Dv];            // Wq|Wk|Wv|Wo hi
__device__ __nv_bfloat16 g_wl[(size_t)4*Dv*Dv];            // Wq|Wk|Wv|Wo lo
__device__ __nv_bfloat16 g_qh[(size_t)Mv*Dv];              // Q (rope, scaled) hi
__device__ __nv_bfloat16 g_ql[(size_t)Mv*Dv];              // Q lo
__device__ __nv_bfloat16 g_kh[(size_t)Mv*Dv];              // K (rope) hi
__device__ __nv_bfloat16 g_kl[(size_t)Mv*Dv];              // K lo
__device__ __nv_bfloat16 g_vh[(size_t)Mv*Dv];              // V hi
__device__ __nv_bfloat16 g_vl[(size_t)Mv*Dv];              // V lo
__device__ __nv_bfloat16 g_ch[(size_t)Mv*Dv];              // ctx hi
__device__ __nv_bfloat16 g_cl[(size_t)Mv*Dv];              // ctx lo

// ---------------------------------------------------------------------------
// helpers
// ---------------------------------------------------------------------------
__device__ __forceinline__ uint32_t smem_u32(const void* p){
    uint32_t a;
    asm("{ .reg .u64 t; cvta.to.shared.u64 t, %1; cvt.u32.u64 %0, t; }" : "=r"(a) : "l"(p));
    return a;
}
__device__ __forceinline__ uint32_t pack_bf2(float x, float y){
    __nv_bfloat162 h = __floats2bfloat162_rn(x, y);
    return *reinterpret_cast<uint32_t*>(&h);
}
__device__ __forceinline__ void ldsm4(uint32_t addr, uint32_t r[4]){
    asm volatile("ldmatrix.sync.aligned.m8n8.x4.shared.b16 {%0,%1,%2,%3}, [%4];"
                 : "=r"(r[0]), "=r"(r[1]), "=r"(r[2]), "=r"(r[3]) : "r"(addr));
}
__device__ __forceinline__ void ldsm4t(uint32_t addr, uint32_t r[4]){
    asm volatile("ldmatrix.sync.aligned.m8n8.x4.trans.shared.b16 {%0,%1,%2,%3}, [%4];"
                 : "=r"(r[0]), "=r"(r[1]), "=r"(r[2]), "=r"(r[3]) : "r"(addr));
}
__device__ __forceinline__ void mma16816(float c[4], const uint32_t a[4], const uint32_t b[2]){
    asm volatile(
        "mma.sync.aligned.m16n8k16.row.col.f32.bf16.bf16.f32 "
        "{%0,%1,%2,%3}, {%4,%5,%6,%7}, {%8,%9}, {%0,%1,%2,%3};"
        : "+f"(c[0]), "+f"(c[1]), "+f"(c[2]), "+f"(c[3])
        : "r"(a[0]), "r"(a[1]), "r"(a[2]), "r"(a[3]), "r"(b[0]), "r"(b[1]));
}
__device__ __forceinline__ void split2(float x, float y, uint32_t& hi, uint32_t& lo){
    float hx = __bfloat162float(__float2bfloat16(x));
    float hy = __bfloat162float(__float2bfloat16(y));
    hi = pack_bf2(hx, hy);
    lo = pack_bf2(x - hx, y - hy);
}
__device__ __forceinline__ void cp16(uint32_t dst, const void* src){
    asm volatile("cp.async.cg.shared.global [%0], [%1], 16;" :: "r"(dst), "l"(src));
}
__device__ __forceinline__ void cp_commit(){
    asm volatile("cp.async.commit_group;" ::: "memory");
}
template<int N>
__device__ __forceinline__ void cp_wait(){
    asm volatile("cp.async.wait_group %0;" :: "n"(N) : "memory");
}

// ---------------------------------------------------------------------------
// fp32 -> bf16 hi/lo planes
// ---------------------------------------------------------------------------
__global__ __launch_bounds__(256)
void split_x(const float* __restrict__ src, __nv_bfloat16* __restrict__ hi,
             __nv_bfloat16* __restrict__ lo, int n8)
{
    const int i = blockIdx.x * blockDim.x + threadIdx.x;
    if (i >= n8) return;
    const float4* s = (const float4*)src + 2*(size_t)i;
    float4 v0 = s[0], v1 = s[1];
    uint32_t h[4], l[4];
    split2(v0.x, v0.y, h[0], l[0]); split2(v0.z, v0.w, h[1], l[1]);
    split2(v1.x, v1.y, h[2], l[2]); split2(v1.z, v1.w, h[3], l[3]);
    ((uint4*)hi)[i] = make_uint4(h[0], h[1], h[2], h[3]);
    ((uint4*)lo)[i] = make_uint4(l[0], l[1], l[2], l[3]);
}

// all 4 weights in one launch (dst planes are contiguous)
__global__ __launch_bounds__(256)
void split_w4(const float* __restrict__ s0, const float* __restrict__ s1,
              const float* __restrict__ s2, const float* __restrict__ s3,
              __nv_bfloat16* __restrict__ hi, __nv_bfloat16* __restrict__ lo)
{
    const size_t i = (size_t)blockIdx.x * blockDim.x + threadIdx.x;  // < 4*WN/8
    const int sel = (int)(i >> 19);                  // WN/8 = 524288 per weight
    const size_t local = i & 524287u;
    const float* src = (sel == 0) ? s0 : (sel == 1) ? s1 : (sel == 2) ? s2 : s3;
    const float4* s = (const float4*)src + 2*local;
    float4 v0 = s[0], v1 = s[1];
    uint32_t h[4], l[4];
    split2(v0.x, v0.y, h[0], l[0]); split2(v0.z, v0.w, h[1], l[1]);
    split2(v1.x, v1.y, h[2], l[2]); split2(v1.z, v1.w, h[3], l[3]);
    ((uint4*)hi)[i] = make_uint4(h[0], h[1], h[2], h[3]);
    ((uint4*)lo)[i] = make_uint4(l[0], l[1], l[2], l[3]);
}

// ---------------------------------------------------------------------------
// Pipelined bf16 GEMM mainloop (3-term hi/lo)  [R11 configuration]
// 128x128 tile, BK=32, 256 threads (8 warps 2x4), 4-stage cp.async pipeline.
// ---------------------------------------------------------------------------
#define SA      40
#define TILE_B  (128*SA*2)      // 10240 B
#define STG_B   (4*TILE_B)      // 40960 B
#define GSM_TOTAL (4*STG_B)     // 163840 B
#define NCH     (Dv/32)         // 64

struct GemmCore {
    float acc[4][4][4];
    int wm, wn, lane;

    __device__ __forceinline__ void run(char* smem,
        const __nv_bfloat16* Ah, const __nv_bfloat16* Al,
        const __nv_bfloat16* Bh, const __nv_bfloat16* Bl,
        int row0, int col0, int tid)
    {
        lane = tid & 31;
        const int wid = tid >> 5;
        wm = wid >> 2;
        wn = wid & 3;
        #pragma unroll
        for (int i = 0; i < 4; i++)
            #pragma unroll
            for (int j = 0; j < 4; j++)
                #pragma unroll
                for (int q = 0; q < 4; q++) acc[i][j][q] = 0.0f;

        const int la_r = (lane & 7) + ((lane >> 3) & 1) * 8;
        const int la_k = (lane >> 4) * 8;
        const int lb_c = (lane & 7) + (lane >> 4) * 8;
        const int lb_k = ((lane >> 3) & 1) * 8;

        const int lrow  = tid >> 1;
        const int lhalf = tid & 1;
        const __nv_bfloat16* aHg = Ah + (size_t)(row0 + lrow) * Dv + lhalf*16;
        const __nv_bfloat16* aLg = Al + (size_t)(row0 + lrow) * Dv + lhalf*16;
        const __nv_bfloat16* bHg = Bh + (size_t)(col0 + lrow) * Dv + lhalf*16;
        const __nv_bfloat16* bLg = Bl + (size_t)(col0 + lrow) * Dv + lhalf*16;
        const uint32_t dsto = (uint32_t)(lrow*(SA*2) + lhalf*32);
        const uint32_t sb = smem_u32(smem);

        #pragma unroll
        for (int s = 0; s < 3; s++) {
            const uint32_t dst = sb + s*STG_B + dsto;
            const size_t go = (size_t)s * 32;
            cp16(dst,               aHg + go);  cp16(dst + 16,            aHg + go + 8);
            cp16(dst +   TILE_B,    aLg + go);  cp16(dst +   TILE_B + 16, aLg + go + 8);
            cp16(dst + 2*TILE_B,    bHg + go);  cp16(dst + 2*TILE_B + 16, bHg + go + 8);
            cp16(dst + 3*TILE_B,    bLg + go);  cp16(dst + 3*TILE_B + 16, bLg + go + 8);
            cp_commit();
        }

        for (int c = 0; c < NCH; c++) {
            cp_wait<2>();
            __syncthreads();

            const uint32_t cur = sb + (c & 3) * STG_B;
            #pragma unroll
            for (int ks = 0; ks < 2; ks++) {
                uint32_t ah[4][4], al[4][4], bh[4][2], bl[4][2];
                #pragma unroll
                for (int mi = 0; mi < 4; mi++) {
                    const uint32_t off = (uint32_t)(((wm*64 + mi*16 + la_r)*SA + ks*16 + la_k) * 2);
                    ldsm4(cur + off,          ah[mi]);
                    ldsm4(cur + TILE_B + off, al[mi]);
                }
                #pragma unroll
                for (int p = 0; p < 2; p++) {
                    const uint32_t off = (uint32_t)(((wn*32 + p*16 + lb_c)*SA + ks*16 + lb_k) * 2);
                    uint32_t t[4];
                    ldsm4(cur + 2*TILE_B + off, t);
                    bh[2*p][0] = t[0]; bh[2*p][1] = t[1];
                    bh[2*p+1][0] = t[2]; bh[2*p+1][1] = t[3];
                    ldsm4(cur + 3*TILE_B + off, t);
                    bl[2*p][0] = t[0]; bl[2*p][1] = t[1];
                    bl[2*p+1][0] = t[2]; bl[2*p+1][1] = t[3];
                }
                #pragma unroll
                for (int mi = 0; mi < 4; mi++)
                    #pragma unroll
                    for (int ni = 0; ni < 4; ni++) {
                        mma16816(acc[mi][ni], ah[mi], bh[ni]);
                        mma16816(acc[mi][ni], al[mi], bh[ni]);
                        mma16816(acc[mi][ni], ah[mi], bl[ni]);
                    }
            }

            if (c + 3 < NCH) {
                const uint32_t dst = sb + ((c+3) & 3) * STG_B + dsto;
                const size_t go = (size_t)(c+3) * 32;
                cp16(dst,               aHg + go);  cp16(dst + 16,            aHg + go + 8);
                cp16(dst +   TILE_B,    aLg + go);  cp16(dst +   TILE_B + 16, aLg + go + 8);
                cp16(dst + 2*TILE_B,    bHg + go);  cp16(dst + 2*TILE_B + 16, bHg + go + 8);
                cp16(dst + 3*TILE_B,    bLg + go);  cp16(dst + 3*TILE_B + 16, bLg + go + 8);
            }
            cp_commit();   // unconditional: keeps group numbering exact
        }
    }
};

// Merged Q/K/V projection GEMM: blockIdx.z = 0(Q) / 1(K) / 2(V)
__global__ __launch_bounds__(256, 1)
void gemm_qkv(const __nv_bfloat16* __restrict__ xh, const __nv_bfloat16* __restrict__ xl,
              const __nv_bfloat16* __restrict__ wh, const __nv_bfloat16* __restrict__ wl,
              const float* __restrict__ fc, const float* __restrict__ fs,
              float* __restrict__ outK, float* __restrict__ outV,
              __nv_bfloat16* __restrict__ qh, __nv_bfloat16* __restrict__ ql,
              __nv_bfloat16* __restrict__ kh, __nv_bfloat16* __restrict__ kl,
              __nv_bfloat16* __restrict__ vh, __nv_bfloat16* __restrict__ vl)
{
    extern __shared__ __align__(1024) char smem[];
    const int z    = blockIdx.z;
    const int row0 = blockIdx.y * 128;
    const int col0 = blockIdx.x * 128;
    const size_t WN = (size_t)Dv*Dv;

    GemmCore core;
    core.run(smem, xh, xl, wh + (size_t)z*WN, wl + (size_t)z*WN, row0, col0, threadIdx.x);

    float* Cf = (z == 1) ? outK : (z == 2) ? outV : nullptr;
    __nv_bfloat16* Ph = (z == 0) ? qh : (z == 1) ? kh : vh;
    __nv_bfloat16* Pl = (z == 0) ? ql : (z == 1) ? kl : vl;
    const bool ROPE = (z <= 1);
    const int lane = core.lane;

    #pragma unroll
    for (int mi = 0; mi < 4; mi++) {
        const int gr0 = row0 + core.wm*64 + mi*16 + (lane >> 2);
        const int gr1 = gr0 + 8;
        #pragma unroll
        for (int ni = 0; ni < 4; ni++) {
            const int gc = col0 + core.wn*32 + ni*8 + (lane & 3)*2;
            float c0 = core.acc[mi][ni][0], c1 = core.acc[mi][ni][1];
            float c2 = core.acc[mi][ni][2], c3 = core.acc[mi][ni][3];
            if (ROPE) {
                const int ip = (gc & (DKv - 1)) >> 1;
                const int s0 = gr0 & (Sv - 1), s1 = gr1 & (Sv - 1);
                float ca = fc[s0*64 + ip], sa = fs[s0*64 + ip];
                float cb = fc[s1*64 + ip], sb2 = fs[s1*64 + ip];
                float t0 = c0*ca - c1*sa, t1 = c0*sa + c1*ca;
                float t2 = c2*cb - c3*sb2, t3 = c2*sb2 + c3*cb;
                c0 = t0; c1 = t1; c2 = t2; c3 = t3;
            }
            if (z == 0) {
                const float s = 0.08838834764831845f;   // 1/sqrt(128)
                c0 *= s; c1 *= s; c2 *= s; c3 *= s;
            } else {
                float2 r0; r0.x = c0; r0.y = c1;
                float2 r1; r1.x = c2; r1.y = c3;
                *(float2*)(Cf + (size_t)gr0 * Dv + gc) = r0;
                *(float2*)(Cf + (size_t)gr1 * Dv + gc) = r1;
            }
            uint32_t h0, l0, h1, l1;
            split2(c0, c1, h0, l0);
            split2(c2, c3, h1, l1);
            *(uint32_t*)(Ph + (size_t)gr0 * Dv + gc) = h0;
            *(uint32_t*)(Pl + (size_t)gr0 * Dv + gc) = l0;
            *(uint32_t*)(Ph + (size_t)gr1 * Dv + gc) = h1;
            *(uint32_t*)(Pl + (size_t)gr1 * Dv + gc) = l1;
        }
    }
}

// Wo GEMM: fp32 out only
__global__ __launch_bounds__(256, 1)
void gemm_wo(const __nv_bfloat16* __restrict__ Ah, const __nv_bfloat16* __restrict__ Al,
             const __nv_bfloat16* __restrict__ Bh, const __nv_bfloat16* __restrict__ Bl,
             float* __restrict__ C)
{
    extern __shared__ __align__(1024) char smem[];
    const int row0 = blockIdx.y * 128;
    const int col0 = blockIdx.x * 128;

    GemmCore core;
    core.run(smem, Ah, Al, Bh, Bl, row0, col0, threadIdx.x);

    const int lane = core.lane;
    #pragma unroll
    for (int mi = 0; mi < 4; mi++) {
        const int gr0 = row0 + core.wm*64 + mi*16 + (lane >> 2);
        const int gr1 = gr0 + 8;
        #pragma unroll
        for (int ni = 0; ni < 4; ni++) {
            const int gc = col0 + core.wn*32 + ni*8 + (lane & 3)*2;
            float2 r0; r0.x = core.acc[mi][ni][0]; r0.y = core.acc[mi][ni][1];
            float2 r1; r1.x = core.acc[mi][ni][2]; r1.y = core.acc[mi][ni][3];
            *(float2*)(C + (size_t)gr0 * Dv + gc) = r0;
            *(float2*)(C + (size_t)gr1 * Dv + gc) = r1;
        }
    }
}

// ---------------------------------------------------------------------------
// Tensor-core flash attention with PV-delayed pipelining.
// BM=128 q-rows/CTA, 256 threads (8 warps x 16 rows). Q hi/lo in smem;
// K/V in a 2-stage combined ring. Per iter: QK(kt) then PV(kt-1) are issued
// BEFORE softmax(kt) -> softmax ALU/MUFU overlaps queued PV tensor work.
// SMEM: Q 2x34816 + 2 stages x (Kh|Kl|Vh|Vl)[64][136] = 208896 B.
// ---------------------------------------------------------------------------
#define SPa     136
#define KT_B    (64*SPa*2)        // 17408 B
#define QT_B    (128*SPa*2)       // 34816 B
#define AST     (4*KT_B)          // 69632 B per KV stage
#define ASM_TOT (2*QT_B + 2*AST)  // 208896 B

__global__ __launch_bounds__(256, 1)
void attn_mma(const __nv_bfloat16* __restrict__ Qh, const __nv_bfloat16* __restrict__ Ql,
              const __nv_bfloat16* __restrict__ Kh, const __nv_bfloat16* __restrict__ Kl,
              const __nv_bfloat16* __restrict__ Vh, const __nv_bfloat16* __restrict__ Vl,
              __nv_bfloat16* __restrict__ ch, __nv_bfloat16* __restrict__ cl)
{
    extern __shared__ __align__(16) char smem[];
    const uint32_t sb = smem_u32(smem);
    const int tid  = threadIdx.x;
    const int lane = tid & 31;
    const int warp = tid >> 5;           // 0..7
    const int qt   = (int)(gridDim.x - 1 - blockIdx.x);   // heavy tiles first
    const int q0   = qt * 128;
    const int h    = blockIdx.y;
    const int b    = blockIdx.z;
    const size_t hoff = (size_t)h * DKv;

    const uint32_t QHo = 0, QLo = QT_B, KVo = 2*QT_B;

    // Q loader: 256 threads -> 128 rows x 2 halves
    const int lrq = tid >> 1;
    const int lcq = (tid & 1) * 64;
    const uint32_t drq = (uint32_t)(lrq*SPa + lcq) * 2;
    const size_t qoff = (size_t)(b*Sv + q0 + lrq) * Dv + hoff + lcq;
    // K/V loader: 256 threads -> 64 rows x 4 quarters
    const int lrk = tid >> 2;
    const int lck = (tid & 3) * 32;
    const uint32_t drk = (uint32_t)(lrk*SPa + lck) * 2;
    const size_t koff0 = (size_t)(b*Sv + lrk) * Dv + hoff + lck;   // + kt*64*Dv

    // prologue: Q (g0), K0 (g1), V0 (g2)
    #pragma unroll
    for (int u = 0; u < 8; u++) {
        cp16(sb + QHo + drq + u*16, Qh + qoff + u*8);
        cp16(sb + QLo + drq + u*16, Ql + qoff + u*8);
    }
    cp_commit();
    {
        const uint32_t base = sb + KVo;
        #pragma unroll
        for (int u = 0; u < 4; u++) {
            cp16(base +        drk + u*16, Kh + koff0 + u*8);
            cp16(base + KT_B + drk + u*16, Kl + koff0 + u*8);
        }
        cp_commit();
        #pragma unroll
        for (int u = 0; u < 4; u++) {
            cp16(base + 2*KT_B + drk + u*16, Vh + koff0 + u*8);
            cp16(base + 3*KT_B + drk + u*16, Vl + koff0 + u*8);
        }
        cp_commit();
    }

    float ctxa[16][4];
    #pragma unroll
    for (int i = 0; i < 16; i++)
        #pragma unroll
        for (int j = 0; j < 4; j++) ctxa[i][j] = 0.0f;
    float m0 = -1e30f, m1 = -1e30f, l0 = 0.0f, l1 = 0.0f;

    uint32_t pah[4][4], pal[4][4];   // P(kt-1) fragments

    const int ktmax = 2*qt + 1;
    for (int kt = 0; kt <= ktmax; kt++) {
        cp_wait<1>();        // K(kt) (+ all older groups incl V(kt-1)) resident
        __syncthreads();
        const uint32_t KB  = sb + KVo + (kt & 1) * AST;
        const uint32_t VBp = sb + KVo + ((kt - 1) & 1) * AST + 2*KT_B;

        // issue K(kt+1): K-half of stage (kt+1)&1, free since QK(kt-1) finished
        if (kt + 1 <= ktmax) {
            const uint32_t base = sb + KVo + ((kt + 1) & 1) * AST;
            const size_t go = koff0 + (size_t)(kt+1)*64*Dv;
            #pragma unroll
            for (int u = 0; u < 4; u++) {
                cp16(base +        drk + u*16, Kh + go + u*8);
                cp16(base + KT_B + drk + u*16, Kl + go + u*8);
            }
        }
        cp_commit();

        // ---- QK(kt): S[16 x 64] per warp over dk=128, hi/lo 3-term ----
        float sc[8][4];
        #pragma unroll
        for (int nt = 0; nt < 8; nt++)
            #pragma unroll
            for (int j = 0; j < 4; j++) sc[nt][j] = 0.0f;

        #pragma unroll
        for (int ks = 0; ks < 8; ks++) {
            uint32_t qh[4], ql[4];
            const uint32_t qaddr = sb + QHo +
                (uint32_t)(((warp*16 + (lane & 15))*SPa + ks*16 + (lane >> 4)*8) * 2);
            ldsm4(qaddr,        qh);
            ldsm4(qaddr + QT_B, ql);
            #pragma unroll
            for (int p = 0; p < 4; p++) {
                const uint32_t kaddr = KB +
                    (uint32_t)(((p*16 + (lane & 15))*SPa + ks*16 + (lane >> 4)*8) * 2);
                uint32_t th[4], tl[4];
                ldsm4(kaddr,        th);
                ldsm4(kaddr + KT_B, tl);
                uint32_t bh0[2] = {th[0], th[2]}, bh1[2] = {th[1], th[3]};
                uint32_t bl0[2] = {tl[0], tl[2]}, bl1[2] = {tl[1], tl[3]};
                mma16816(sc[2*p],   qh, bh0);
                mma16816(sc[2*p],   ql, bh0);
                mma16816(sc[2*p],   qh, bl0);
                mma16816(sc[2*p+1], qh, bh1);
                mma16816(sc[2*p+1], ql, bh1);
                mma16816(sc[2*p+1], qh, bl1);
            }
        }

        // ---- PV(kt-1): queued behind QK; executes while softmax runs ----
        if (kt > 0) {
            #pragma unroll
            for (int k2 = 0; k2 < 4; k2++) {
                #pragma unroll
                for (int p = 0; p < 8; p++) {
                    const uint32_t vaddr = VBp +
                        (uint32_t)(((k2*16 + (lane & 15))*SPa + p*16 + (lane >> 4)*8) * 2);
                    uint32_t vh[4], vl[4];
                    ldsm4t(vaddr,        vh);
                    ldsm4t(vaddr + KT_B, vl);
                    uint32_t bh0[2] = {vh[0], vh[1]}, bh1[2] = {vh[2], vh[3]};
                    uint32_t bl0[2] = {vl[0], vl[1]}, bl1[2] = {vl[2], vl[3]};
                    mma16816(ctxa[2*p],   pah[k2], bh0);
                    mma16816(ctxa[2*p],   pal[k2], bh0);
                    mma16816(ctxa[2*p],   pah[k2], bl0);
                    mma16816(ctxa[2*p+1], pah[k2], bh1);
                    mma16816(ctxa[2*p+1], pal[k2], bh1);
                    mma16816(ctxa[2*p+1], pah[k2], bl1);
                }
            }
        }
        __syncthreads();   // all warps done reading V(kt-1) half -> refill it

        // issue V(kt+1): V-half of stage (kt+1)&1 (same stage PV(kt-1) just read)
        if (kt + 1 <= ktmax) {
            const uint32_t base = sb + KVo + ((kt + 1) & 1) * AST;
            const size_t go = koff0 + (size_t)(kt+1)*64*Dv;
            #pragma unroll
            for (int u = 0; u < 4; u++) {
                cp16(base + 2*KT_B + drk + u*16, Vh + go + u*8);
                cp16(base + 3*KT_B + drk + u*16, Vl + go + u*8);
            }
        }
        cp_commit();

        // ---- softmax(kt) (overlaps PV(kt-1) tensor work) ----
        const int gr0 = q0 + warp*16 + (lane >> 2);
        const int gr1 = gr0 + 8;
        if (kt >= 2*qt) {    // only the last two tiles can cross the diagonal
            #pragma unroll
            for (int nt = 0; nt < 8; nt++) {
                const int cb = kt*64 + nt*8 + (lane & 3)*2;
                if (cb     > gr0) sc[nt][0] = -1e30f;
                if (cb + 1 > gr0) sc[nt][1] = -1e30f;
                if (cb     > gr1) sc[nt][2] = -1e30f;
                if (cb + 1 > gr1) sc[nt][3] = -1e30f;
            }
        }
        float mx0 = -1e30f, mx1 = -1e30f;
        #pragma unroll
        for (int nt = 0; nt < 8; nt++) {
            mx0 = fmaxf(mx0, fmaxf(sc[nt][0], sc[nt][1]));
            mx1 = fmaxf(mx1, fmaxf(sc[nt][2], sc[nt][3]));
        }
        mx0 = fmaxf(mx0, __shfl_xor_sync(0xffffffffu, mx0, 1));
        mx0 = fmaxf(mx0, __shfl_xor_sync(0xffffffffu, mx0, 2));
        mx1 = fmaxf(mx1, __shfl_xor_sync(0xffffffffu, mx1, 1));
        mx1 = fmaxf(mx1, __shfl_xor_sync(0xffffffffu, mx1, 2));

        const float mn0 = fmaxf(m0, mx0), mn1 = fmaxf(m1, mx1);
        const float a0 = __expf(m0 - mn0), a1 = __expf(m1 - mn1);
        m0 = mn0; m1 = mn1;

        float s0 = 0.0f, s1 = 0.0f;
        #pragma unroll
        for (int nt = 0; nt < 8; nt++) {
            sc[nt][0] = __expf(sc[nt][0] - mn0);
            sc[nt][1] = __expf(sc[nt][1] - mn0);
            sc[nt][2] = __expf(sc[nt][2] - mn1);
            sc[nt][3] = __expf(sc[nt][3] - mn1);
            s0 += sc[nt][0] + sc[nt][1];
            s1 += sc[nt][2] + sc[nt][3];
        }
        s0 += __shfl_xor_sync(0xffffffffu, s0, 1);
        s0 += __shfl_xor_sync(0xffffffffu, s0, 2);
        s1 += __shfl_xor_sync(0xffffffffu, s1, 1);
        s1 += __shfl_xor_sync(0xffffffffu, s1, 2);
        l0 = l0 * a0 + s0;
        l1 = l1 * a1 + s1;

        // pack P(kt) for next iteration's PV
        #pragma unroll
        for (int k2 = 0; k2 < 4; k2++) {
            split2(sc[2*k2][0],   sc[2*k2][1],   pah[k2][0], pal[k2][0]);
            split2(sc[2*k2][2],   sc[2*k2][3],   pah[k2][1], pal[k2][1]);
            split2(sc[2*k2+1][0], sc[2*k2+1][1], pah[k2][2], pal[k2][2]);
            split2(sc[2*k2+1][2], sc[2*k2+1][3], pah[k2][3], pal[k2][3]);
        }

        // rescale ctx LAST (waits on PV(kt-1) completion as late as possible)
        #pragma unroll
        for (int nt = 0; nt < 16; nt++) {
            ctxa[nt][0] *= a0; ctxa[nt][1] *= a0;
            ctxa[nt][2] *= a1; ctxa[nt][3] *= a1;
        }
    }

    // final PV(ktmax)
    {
        const uint32_t VB = sb + KVo + (ktmax & 1) * AST + 2*KT_B;
        #pragma unroll
        for (int k2 = 0; k2 < 4; k2++) {
            #pragma unroll
            for (int p = 0; p < 8; p++) {
                const uint32_t vaddr = VB +
                    (uint32_t)(((k2*16 + (lane & 15))*SPa + p*16 + (lane >> 4)*8) * 2);
                uint32_t vh[4], vl[4];
                ldsm4t(vaddr,        vh);
                ldsm4t(vaddr + KT_B, vl);
                uint32_t bh0[2] = {vh[0], vh[1]}, bh1[2] = {vh[2], vh[3]};
                uint32_t bl0[2] = {vl[0], vl[1]}, bl1[2] = {vl[2], vl[3]};
                mma16816(ctxa[2*p],   pah[k2], bh0);
                mma16816(ctxa[2*p],   pal[k2], bh0);
                mma16816(ctxa[2*p],   pah[k2], bl0);
                mma16816(ctxa[2*p+1], pah[k2], bh1);
                mma16816(ctxa[2*p+1], pal[k2], bh1);
                mma16816(ctxa[2*p+1], pah[k2], bl1);
            }
        }
    }

    // epilogue: ctx/l -> bf16 hi/lo planes
    const float i0 = 1.0f / l0, i1 = 1.0f / l1;
    const size_t r0g = (size_t)(b*Sv + q0 + warp*16 + (lane >> 2));
    const size_t r1g = r0g + 8;
    #pragma unroll
    for (int nt = 0; nt < 16; nt++) {
        const size_t col = hoff + nt*8 + (lane & 3)*2;
        uint32_t h0, l0u, h1, l1u;
        split2(ctxa[nt][0]*i0, ctxa[nt][1]*i0, h0, l0u);
        split2(ctxa[nt][2]*i1, ctxa[nt][3]*i1, h1, l1u);
        *(uint32_t*)(ch + r0g*Dv + col) = h0;
        *(uint32_t*)(cl + r0g*Dv + col) = l0u;
        *(uint32_t*)(ch + r1g*Dv + col) = h1;
        *(uint32_t*)(cl + r1g*Dv + col) = l1u;
    }
}

// ---------------------------------------------------------------------------
extern "C" void kernel_launch(void* const* d_in, const int* in_sizes, int n_in,
                              void* d_out, int out_size)
{
    const float* x  = (const float*)d_in[0];
    const float* fc = (const float*)d_in[1];
    const float* fs = (const float*)d_in[2];
    // d_in[3] = mask (unused: -1e9 mask == strict causal in f32)
    const float* Wq = (const float*)d_in[4];
    const float* Wk = (const float*)d_in[5];
    const float* Wv = (const float*)d_in[6];
    const float* Wo = (const float*)d_in[7];

    float* out  = (float*)d_out;
    float* outK = out  + (size_t)Mv*Dv;
    float* outV = outK + (size_t)Mv*Dv;

    __nv_bfloat16 *xh, *xl, *wh, *wl, *qh, *ql, *kh, *kl, *vh, *vl, *ch, *cl;
    cudaGetSymbolAddress((void**)&xh, g_xh);
    cudaGetSymbolAddress((void**)&xl, g_xl);
    cudaGetSymbolAddress((void**)&wh, g_wh);
    cudaGetSymbolAddress((void**)&wl, g_wl);
    cudaGetSymbolAddress((void**)&qh, g_qh);
    cudaGetSymbolAddress((void**)&ql, g_ql);
    cudaGetSymbolAddress((void**)&kh, g_kh);
    cudaGetSymbolAddress((void**)&kl, g_kl);
    cudaGetSymbolAddress((void**)&vh, g_vh);
    cudaGetSymbolAddress((void**)&vl, g_vl);
    cudaGetSymbolAddress((void**)&ch, g_ch);
    cudaGetSymbolAddress((void**)&cl, g_cl);

    cudaFuncSetAttribute(gemm_qkv, cudaFuncAttributeMaxDynamicSharedMemorySize, GSM_TOTAL);
    cudaFuncSetAttribute(gemm_wo,  cudaFuncAttributeMaxDynamicSharedMemorySize, GSM_TOTAL);
    cudaFuncSetAttribute(attn_mma, cudaFuncAttributeMaxDynamicSharedMemorySize, ASM_TOT);

    const size_t WN = (size_t)Dv*Dv;     // 4M elems per weight

    split_x<<<(Mv*Dv/8 + 255)/256, 256>>>(x, xh, xl, Mv*Dv/8);
    split_w4<<<(int)(4*WN/8/256), 256>>>(Wq, Wk, Wv, Wo, wh, wl);

    dim3 ggrid(Dv/128, Mv/128, 3);   // (16, 32, 3)
    gemm_qkv<<<ggrid, 256, GSM_TOTAL>>>(xh, xl, wh, wl, fc, fs, outK, outV,
                                        qh, ql, kh, kl, vh, vl);

    attn_mma<<<dim3(Sv/128, Hv, Bv), 256, ASM_TOT>>>(qh, ql, kh, kl, vh, vl, ch, cl);

    gemm_wo<<<dim3(Dv/128, Mv/128), 256, GSM_TOTAL>>>(ch, cl, wh + 3*WN, wl + 3*WN, out);
}

// round 16
// speedup vs baseline: 1.1366x; 1.1240x over previous
#include <cuda_runtime.h>
#include <cuda_bf16.h>
#include <math.h>
#include <stdint.h>

#define Bv  2
#define Sv  2048
#define Dv  2048
#define Hv  16
#define DKv 128
#define Mv  (Bv*Sv)   // 4096

// Scratch (allocation-free rule: __device__ globals)
__device__ __nv_bfloat16 g_xh[(size_t)Mv*Dv];              // x hi
__device__ __nv_bfloat16 g_xl[(size_t)Mv*Dv];              // x lo
__device__ __nv_bfloat16 g_wh[(size_t)4*Dv*Dv];            // Wq|Wk|Wv|Wo hi
__device__ __nv_bfloat16 g_wl[(size_t)4*Dv*Dv];            // Wq|Wk|Wv|Wo lo
__device__ __nv_bfloat16 g_qh[(size_t)Mv*Dv];              // Q (rope, scaled) hi
__device__ __nv_bfloat16 g_ql[(size_t)Mv*Dv];              // Q lo
__device__ __nv_bfloat16 g_kh[(size_t)Mv*Dv];              // K (rope) hi
__device__ __nv_bfloat16 g_kl[(size_t)Mv*Dv];              // K lo
__device__ __nv_bfloat16 g_vh[(size_t)Mv*Dv];              // V hi
__device__ __nv_bfloat16 g_vl[(size_t)Mv*Dv];              // V lo
__device__ __nv_bfloat16 g_ch[(size_t)Mv*Dv];              // ctx hi
__device__ __nv_bfloat16 g_cl[(size_t)Mv*Dv];              // ctx lo

// ---------------------------------------------------------------------------
// helpers
// ---------------------------------------------------------------------------
__device__ __forceinline__ uint32_t smem_u32(const void* p){
    uint32_t a;
    asm("{ .reg .u64 t; cvta.to.shared.u64 t, %1; cvt.u32.u64 %0, t; }" : "=r"(a) : "l"(p));
    return a;
}
__device__ __forceinline__ uint32_t pack_bf2(float x, float y){
    __nv_bfloat162 h = __floats2bfloat162_rn(x, y);
    return *reinterpret_cast<uint32_t*>(&h);
}
__device__ __forceinline__ void ldsm4(uint32_t addr, uint32_t r[4]){
    asm volatile("ldmatrix.sync.aligned.m8n8.x4.shared.b16 {%0,%1,%2,%3}, [%4];"
                 : "=r"(r[0]), "=r"(r[1]), "=r"(r[2]), "=r"(r[3]) : "r"(addr));
}
__device__ __forceinline__ void ldsm4t(uint32_t addr, uint32_t r[4]){
    asm volatile("ldmatrix.sync.aligned.m8n8.x4.trans.shared.b16 {%0,%1,%2,%3}, [%4];"
                 : "=r"(r[0]), "=r"(r[1]), "=r"(r[2]), "=r"(r[3]) : "r"(addr));
}
__device__ __forceinline__ void mma16816(float c[4], const uint32_t a[4], const uint32_t b[2]){
    asm volatile(
        "mma.sync.aligned.m16n8k16.row.col.f32.bf16.bf16.f32 "
        "{%0,%1,%2,%3}, {%4,%5,%6,%7}, {%8,%9}, {%0,%1,%2,%3};"
        : "+f"(c[0]), "+f"(c[1]), "+f"(c[2]), "+f"(c[3])
        : "r"(a[0]), "r"(a[1]), "r"(a[2]), "r"(a[3]), "r"(b[0]), "r"(b[1]));
}
__device__ __forceinline__ void split2(float x, float y, uint32_t& hi, uint32_t& lo){
    float hx = __bfloat162float(__float2bfloat16(x));
    float hy = __bfloat162float(__float2bfloat16(y));
    hi = pack_bf2(hx, hy);
    lo = pack_bf2(x - hx, y - hy);
}
__device__ __forceinline__ void cp16(uint32_t dst, const void* src){
    asm volatile("cp.async.cg.shared.global [%0], [%1], 16;" :: "r"(dst), "l"(src));
}
__device__ __forceinline__ void cp_commit(){
    asm volatile("cp.async.commit_group;" ::: "memory");
}
template<int N>
__device__ __forceinline__ void cp_wait(){
    asm volatile("cp.async.wait_group %0;" :: "n"(N) : "memory");
}

// ---------------------------------------------------------------------------
// fp32 -> bf16 hi/lo planes
// ---------------------------------------------------------------------------
__global__ __launch_bounds__(256)
void split_x(const float* __restrict__ src, __nv_bfloat16* __restrict__ hi,
             __nv_bfloat16* __restrict__ lo, int n8)
{
    const int i = blockIdx.x * blockDim.x + threadIdx.x;
    if (i >= n8) return;
    const float4* s = (const float4*)src + 2*(size_t)i;
    float4 v0 = s[0], v1 = s[1];
    uint32_t h[4], l[4];
    split2(v0.x, v0.y, h[0], l[0]); split2(v0.z, v0.w, h[1], l[1]);
    split2(v1.x, v1.y, h[2], l[2]); split2(v1.z, v1.w, h[3], l[3]);
    ((uint4*)hi)[i] = make_uint4(h[0], h[1], h[2], h[3]);
    ((uint4*)lo)[i] = make_uint4(l[0], l[1], l[2], l[3]);
}

// all 4 weights in one launch (dst planes are contiguous)
__global__ __launch_bounds__(256)
void split_w4(const float* __restrict__ s0, const float* __restrict__ s1,
              const float* __restrict__ s2, const float* __restrict__ s3,
              __nv_bfloat16* __restrict__ hi, __nv_bfloat16* __restrict__ lo)
{
    const size_t i = (size_t)blockIdx.x * blockDim.x + threadIdx.x;  // < 4*WN/8
    const int sel = (int)(i >> 19);                  // WN/8 = 524288 per weight
    const size_t local = i & 524287u;
    const float* src = (sel == 0) ? s0 : (sel == 1) ? s1 : (sel == 2) ? s2 : s3;
    const float4* s = (const float4*)src + 2*local;
    float4 v0 = s[0], v1 = s[1];
    uint32_t h[4], l[4];
    split2(v0.x, v0.y, h[0], l[0]); split2(v0.z, v0.w, h[1], l[1]);
    split2(v1.x, v1.y, h[2], l[2]); split2(v1.z, v1.w, h[3], l[3]);
    ((uint4*)hi)[i] = make_uint4(h[0], h[1], h[2], h[3]);
    ((uint4*)lo)[i] = make_uint4(l[0], l[1], l[2], l[3]);
}

// ---------------------------------------------------------------------------
// Pipelined bf16 GEMM mainloop (3-term hi/lo), 512 threads.
// 128x128 tile, BK=32, 16 warps (4x4 grid, 32x32 warp tiles) -> 4 warps/SMSP
// for latency hiding; term-major MMA order breaks accumulator RAW chains.
// 4-stage cp.async pipeline (same as R11).
// ---------------------------------------------------------------------------
#define SA      40
#define TILE_B  (128*SA*2)      // 10240 B
#define STG_B   (4*TILE_B)      // 40960 B
#define GSM_TOTAL (4*STG_B)     // 163840 B
#define NCH     (Dv/32)         // 64
#define GTHREADS 512

struct GemmCore {
    float acc[2][4][4];
    int wm, wn, lane;

    __device__ __forceinline__ void run(char* smem,
        const __nv_bfloat16* Ah, const __nv_bfloat16* Al,
        const __nv_bfloat16* Bh, const __nv_bfloat16* Bl,
        int row0, int col0, int tid)
    {
        lane = tid & 31;
        const int wid = tid >> 5;      // 0..15
        wm = wid >> 2;                 // 0..3 -> 32-row band
        wn = wid & 3;                  // 0..3 -> 32-col band
        #pragma unroll
        for (int i = 0; i < 2; i++)
            #pragma unroll
            for (int j = 0; j < 4; j++)
                #pragma unroll
                for (int q = 0; q < 4; q++) acc[i][j][q] = 0.0f;

        const int la_r = (lane & 7) + ((lane >> 3) & 1) * 8;
        const int la_k = (lane >> 4) * 8;
        const int lb_c = (lane & 7) + (lane >> 4) * 8;
        const int lb_k = ((lane >> 3) & 1) * 8;

        // loader: 512 threads -> 128 rows x 4 quarters (16B each)
        const int lrow = tid >> 2;
        const int lq   = tid & 3;
        const __nv_bfloat16* aHg = Ah + (size_t)(row0 + lrow) * Dv + lq*8;
        const __nv_bfloat16* aLg = Al + (size_t)(row0 + lrow) * Dv + lq*8;
        const __nv_bfloat16* bHg = Bh + (size_t)(col0 + lrow) * Dv + lq*8;
        const __nv_bfloat16* bLg = Bl + (size_t)(col0 + lrow) * Dv + lq*8;
        const uint32_t dsto = (uint32_t)(lrow*(SA*2) + lq*16);
        const uint32_t sb = smem_u32(smem);

        #pragma unroll
        for (int s = 0; s < 3; s++) {
            const uint32_t dst = sb + s*STG_B + dsto;
            const size_t go = (size_t)s * 32;
            cp16(dst,            aHg + go);
            cp16(dst +   TILE_B, aLg + go);
            cp16(dst + 2*TILE_B, bHg + go);
            cp16(dst + 3*TILE_B, bLg + go);
            cp_commit();
        }

        for (int c = 0; c < NCH; c++) {
            cp_wait<2>();
            __syncthreads();

            const uint32_t cur = sb + (c & 3) * STG_B;
            #pragma unroll
            for (int ks = 0; ks < 2; ks++) {
                uint32_t ah[2][4], al[2][4], bh[4][2], bl[4][2];
                #pragma unroll
                for (int mi = 0; mi < 2; mi++) {
                    const uint32_t off = (uint32_t)(((wm*32 + mi*16 + la_r)*SA + ks*16 + la_k) * 2);
                    ldsm4(cur + off,          ah[mi]);
                    ldsm4(cur + TILE_B + off, al[mi]);
                }
                #pragma unroll
                for (int p = 0; p < 2; p++) {
                    const uint32_t off = (uint32_t)(((wn*32 + p*16 + lb_c)*SA + ks*16 + lb_k) * 2);
                    uint32_t t[4];
                    ldsm4(cur + 2*TILE_B + off, t);
                    bh[2*p][0] = t[0]; bh[2*p][1] = t[1];
                    bh[2*p+1][0] = t[2]; bh[2*p+1][1] = t[3];
                    ldsm4(cur + 3*TILE_B + off, t);
                    bl[2*p][0] = t[0]; bl[2*p][1] = t[1];
                    bl[2*p+1][0] = t[2]; bl[2*p+1][1] = t[3];
                }
                // term-major: same-acc MMAs are 8 apart (no RAW chains)
                #pragma unroll
                for (int mi = 0; mi < 2; mi++)
                    #pragma unroll
                    for (int ni = 0; ni < 4; ni++)
                        mma16816(acc[mi][ni], ah[mi], bh[ni]);
                #pragma unroll
                for (int mi = 0; mi < 2; mi++)
                    #pragma unroll
                    for (int ni = 0; ni < 4; ni++)
                        mma16816(acc[mi][ni], al[mi], bh[ni]);
                #pragma unroll
                for (int mi = 0; mi < 2; mi++)
                    #pragma unroll
                    for (int ni = 0; ni < 4; ni++)
                        mma16816(acc[mi][ni], ah[mi], bl[ni]);
            }

            if (c + 3 < NCH) {
                const uint32_t dst = sb + ((c+3) & 3) * STG_B + dsto;
                const size_t go = (size_t)(c+3) * 32;
                cp16(dst,            aHg + go);
                cp16(dst +   TILE_B, aLg + go);
                cp16(dst + 2*TILE_B, bHg + go);
                cp16(dst + 3*TILE_B, bLg + go);
            }
            cp_commit();   // unconditional: keeps group numbering exact
        }
    }
};

// Merged Q/K/V projection GEMM: blockIdx.z = 0(Q) / 1(K) / 2(V)
__global__ __launch_bounds__(GTHREADS, 1)
void gemm_qkv(const __nv_bfloat16* __restrict__ xh, const __nv_bfloat16* __restrict__ xl,
              const __nv_bfloat16* __restrict__ wh, const __nv_bfloat16* __restrict__ wl,
              const float* __restrict__ fc, const float* __restrict__ fs,
              float* __restrict__ outK, float* __restrict__ outV,
              __nv_bfloat16* __restrict__ qh, __nv_bfloat16* __restrict__ ql,
              __nv_bfloat16* __restrict__ kh, __nv_bfloat16* __restrict__ kl,
              __nv_bfloat16* __restrict__ vh, __nv_bfloat16* __restrict__ vl)
{
    extern __shared__ __align__(1024) char smem[];
    const int z    = blockIdx.z;
    const int row0 = blockIdx.y * 128;
    const int col0 = blockIdx.x * 128;
    const size_t WN = (size_t)Dv*Dv;

    GemmCore core;
    core.run(smem, xh, xl, wh + (size_t)z*WN, wl + (size_t)z*WN, row0, col0, threadIdx.x);

    float* Cf = (z == 1) ? outK : (z == 2) ? outV : nullptr;
    __nv_bfloat16* Ph = (z == 0) ? qh : (z == 1) ? kh : vh;
    __nv_bfloat16* Pl = (z == 0) ? ql : (z == 1) ? kl : vl;
    const bool ROPE = (z <= 1);
    const int lane = core.lane;

    #pragma unroll
    for (int mi = 0; mi < 2; mi++) {
        const int gr0 = row0 + core.wm*32 + mi*16 + (lane >> 2);
        const int gr1 = gr0 + 8;
        #pragma unroll
        for (int ni = 0; ni < 4; ni++) {
            const int gc = col0 + core.wn*32 + ni*8 + (lane & 3)*2;
            float c0 = core.acc[mi][ni][0], c1 = core.acc[mi][ni][1];
            float c2 = core.acc[mi][ni][2], c3 = core.acc[mi][ni][3];
            if (ROPE) {
                const int ip = (gc & (DKv - 1)) >> 1;
                const int s0 = gr0 & (Sv - 1), s1 = gr1 & (Sv - 1);
                float ca = fc[s0*64 + ip], sa = fs[s0*64 + ip];
                float cb = fc[s1*64 + ip], sb2 = fs[s1*64 + ip];
                float t0 = c0*ca - c1*sa, t1 = c0*sa + c1*ca;
                float t2 = c2*cb - c3*sb2, t3 = c2*sb2 + c3*cb;
                c0 = t0; c1 = t1; c2 = t2; c3 = t3;
            }
            if (z == 0) {
                const float s = 0.08838834764831845f;   // 1/sqrt(128)
                c0 *= s; c1 *= s; c2 *= s; c3 *= s;
            } else {
                float2 r0; r0.x = c0; r0.y = c1;
                float2 r1; r1.x = c2; r1.y = c3;
                *(float2*)(Cf + (size_t)gr0 * Dv + gc) = r0;
                *(float2*)(Cf + (size_t)gr1 * Dv + gc) = r1;
            }
            uint32_t h0, l0, h1, l1;
            split2(c0, c1, h0, l0);
            split2(c2, c3, h1, l1);
            *(uint32_t*)(Ph + (size_t)gr0 * Dv + gc) = h0;
            *(uint32_t*)(Pl + (size_t)gr0 * Dv + gc) = l0;
            *(uint32_t*)(Ph + (size_t)gr1 * Dv + gc) = h1;
            *(uint32_t*)(Pl + (size_t)gr1 * Dv + gc) = l1;
        }
    }
}

// Wo GEMM: fp32 out only
__global__ __launch_bounds__(GTHREADS, 1)
void gemm_wo(const __nv_bfloat16* __restrict__ Ah, const __nv_bfloat16* __restrict__ Al,
             const __nv_bfloat16* __restrict__ Bh, const __nv_bfloat16* __restrict__ Bl,
             float* __restrict__ C)
{
    extern __shared__ __align__(1024) char smem[];
    const int row0 = blockIdx.y * 128;
    const int col0 = blockIdx.x * 128;

    GemmCore core;
    core.run(smem, Ah, Al, Bh, Bl, row0, col0, threadIdx.x);

    const int lane = core.lane;
    #pragma unroll
    for (int mi = 0; mi < 2; mi++) {
        const int gr0 = row0 + core.wm*32 + mi*16 + (lane >> 2);
        const int gr1 = gr0 + 8;
        #pragma unroll
        for (int ni = 0; ni < 4; ni++) {
            const int gc = col0 + core.wn*32 + ni*8 + (lane & 3)*2;
            float2 r0; r0.x = core.acc[mi][ni][0]; r0.y = core.acc[mi][ni][1];
            float2 r1; r1.x = core.acc[mi][ni][2]; r1.y = core.acc[mi][ni][3];
            *(float2*)(C + (size_t)gr0 * Dv + gc) = r0;
            *(float2*)(C + (size_t)gr1 * Dv + gc) = r1;
        }
    }
}

// ---------------------------------------------------------------------------
// Tensor-core flash attention [R11 configuration, verbatim].
// BM=128 q-rows/CTA, 256 threads (8 warps x 16 rows), kv tiles 64 wide.
// SMEM: Q hi/lo [128][136] + K,V hi/lo [64][136] = 139264 B -> 1 CTA/SM.
// ---------------------------------------------------------------------------
#define SP      136
#define QTILE   (128*SP*2)       // 34816 B
#define KTILE   (64*SP*2)        // 17408 B
#define ASM_TOT (2*QTILE + 4*KTILE)   // 139264 B

__global__ __launch_bounds__(256, 1)
void attn_mma(const __nv_bfloat16* __restrict__ Qh, const __nv_bfloat16* __restrict__ Ql,
              const __nv_bfloat16* __restrict__ Kh, const __nv_bfloat16* __restrict__ Kl,
              const __nv_bfloat16* __restrict__ Vh, const __nv_bfloat16* __restrict__ Vl,
              __nv_bfloat16* __restrict__ ch, __nv_bfloat16* __restrict__ cl)
{
    extern __shared__ __align__(16) char smem[];
    const uint32_t sb = smem_u32(smem);
    const int tid  = threadIdx.x;
    const int lane = tid & 31;
    const int warp = tid >> 5;           // 0..7
    const int qt   = blockIdx.x;
    const int q0   = qt * 128;
    const int h    = blockIdx.y;
    const int b    = blockIdx.z;
    const size_t hoff = (size_t)h * DKv;

    const uint32_t QH = 0, QL = QTILE, KH = 2*QTILE, VH = 2*QTILE + 2*KTILE;

    const int lrq = tid >> 1;
    const int lcq = (tid & 1) * 64;
    const uint32_t drq = (uint32_t)(lrq*SP + lcq) * 2;
    const size_t qoff = (size_t)(b*Sv + q0 + lrq) * Dv + hoff + lcq;
    const int lrk = tid >> 2;
    const int lck = (tid & 3) * 32;
    const uint32_t drk = (uint32_t)(lrk*SP + lck) * 2;
    const size_t koff0 = (size_t)(b*Sv + lrk) * Dv + hoff + lck;   // + kt*64*Dv

    // prologue: Q + K_0 in one group
    #pragma unroll
    for (int u = 0; u < 8; u++) {
        cp16(sb + QH + drq + u*16, Qh + qoff + u*8);
        cp16(sb + QL + drq + u*16, Ql + qoff + u*8);
    }
    #pragma unroll
    for (int u = 0; u < 4; u++) {
        cp16(sb + KH +         drk + u*16, Kh + koff0 + u*8);
        cp16(sb + KH + KTILE + drk + u*16, Kl + koff0 + u*8);
    }
    cp_commit();

    float ctxa[16][4];
    #pragma unroll
    for (int i = 0; i < 16; i++)
        #pragma unroll
        for (int j = 0; j < 4; j++) ctxa[i][j] = 0.0f;
    float m0 = -1e30f, m1 = -1e30f, l0 = 0.0f, l1 = 0.0f;

    const int ktmax = 2*qt + 1;
    for (int kt = 0; kt <= ktmax; kt++) {
        // V_kt (overlaps QK); barrier first: prev PV must be done with V smem
        __syncthreads();
        {
            const size_t vo = koff0 + (size_t)kt*64*Dv;
            #pragma unroll
            for (int u = 0; u < 4; u++) {
                cp16(sb + VH +         drk + u*16, Vh + vo + u*8);
                cp16(sb + VH + KTILE + drk + u*16, Vl + vo + u*8);
            }
        }
        cp_commit();
        cp_wait<1>();        // K_kt (and Q) ready
        __syncthreads();

        // ---- scores: S[16 x 64] per warp over dk=128, hi/lo 3-term ----
        float sc[8][4];
        #pragma unroll
        for (int nt = 0; nt < 8; nt++)
            #pragma unroll
            for (int j = 0; j < 4; j++) sc[nt][j] = 0.0f;

        #pragma unroll
        for (int ks = 0; ks < 8; ks++) {
            uint32_t qh[4], ql[4];
            const uint32_t qaddr = sb + QH +
                (uint32_t)(((warp*16 + (lane & 15))*SP + ks*16 + (lane >> 4)*8) * 2);
            ldsm4(qaddr,         qh);
            ldsm4(qaddr + QTILE, ql);
            #pragma unroll
            for (int p = 0; p < 4; p++) {
                const uint32_t kaddr = sb + KH +
                    (uint32_t)(((p*16 + (lane & 15))*SP + ks*16 + (lane >> 4)*8) * 2);
                uint32_t th[4], tl[4];
                ldsm4(kaddr,         th);
                ldsm4(kaddr + KTILE, tl);
                uint32_t bh0[2] = {th[0], th[2]}, bh1[2] = {th[1], th[3]};
                uint32_t bl0[2] = {tl[0], tl[2]}, bl1[2] = {tl[1], tl[3]};
                mma16816(sc[2*p],   qh, bh0);
                mma16816(sc[2*p],   ql, bh0);
                mma16816(sc[2*p],   qh, bl0);
                mma16816(sc[2*p+1], qh, bh1);
                mma16816(sc[2*p+1], ql, bh1);
                mma16816(sc[2*p+1], qh, bl1);
            }
        }

        // ---- softmax ----
        const int gr0 = q0 + warp*16 + (lane >> 2);
        const int gr1 = gr0 + 8;
        if (kt >= 2*qt) {    // only the last two tiles can cross the diagonal
            #pragma unroll
            for (int nt = 0; nt < 8; nt++) {
                const int cb = kt*64 + nt*8 + (lane & 3)*2;
                if (cb     > gr0) sc[nt][0] = -1e30f;
                if (cb + 1 > gr0) sc[nt][1] = -1e30f;
                if (cb     > gr1) sc[nt][2] = -1e30f;
                if (cb + 1 > gr1) sc[nt][3] = -1e30f;
            }
        }
        float mx0 = -1e30f, mx1 = -1e30f;
        #pragma unroll
        for (int nt = 0; nt < 8; nt++) {
            mx0 = fmaxf(mx0, fmaxf(sc[nt][0], sc[nt][1]));
            mx1 = fmaxf(mx1, fmaxf(sc[nt][2], sc[nt][3]));
        }
        mx0 = fmaxf(mx0, __shfl_xor_sync(0xffffffffu, mx0, 1));
        mx0 = fmaxf(mx0, __shfl_xor_sync(0xffffffffu, mx0, 2));
        mx1 = fmaxf(mx1, __shfl_xor_sync(0xffffffffu, mx1, 1));
        mx1 = fmaxf(mx1, __shfl_xor_sync(0xffffffffu, mx1, 2));

        const float mn0 = fmaxf(m0, mx0), mn1 = fmaxf(m1, mx1);
        const float a0 = __expf(m0 - mn0), a1 = __expf(m1 - mn1);
        m0 = mn0; m1 = mn1;

        float s0 = 0.0f, s1 = 0.0f;
        #pragma unroll
        for (int nt = 0; nt < 8; nt++) {
            sc[nt][0] = __expf(sc[nt][0] - mn0);
            sc[nt][1] = __expf(sc[nt][1] - mn0);
            sc[nt][2] = __expf(sc[nt][2] - mn1);
            sc[nt][3] = __expf(sc[nt][3] - mn1);
            s0 += sc[nt][0] + sc[nt][1];
            s1 += sc[nt][2] + sc[nt][3];
        }
        s0 += __shfl_xor_sync(0xffffffffu, s0, 1);
        s0 += __shfl_xor_sync(0xffffffffu, s0, 2);
        s1 += __shfl_xor_sync(0xffffffffu, s1, 1);
        s1 += __shfl_xor_sync(0xffffffffu, s1, 2);
        l0 = l0 * a0 + s0;
        l1 = l1 * a1 + s1;

        #pragma unroll
        for (int nt = 0; nt < 16; nt++) {
            ctxa[nt][0] *= a0; ctxa[nt][1] *= a0;
            ctxa[nt][2] *= a1; ctxa[nt][3] *= a1;
        }

        // pack P (C-frag -> A-frag), hi/lo
        uint32_t pah[4][4], pal[4][4];
        #pragma unroll
        for (int k2 = 0; k2 < 4; k2++) {
            split2(sc[2*k2][0],   sc[2*k2][1],   pah[k2][0], pal[k2][0]);
            split2(sc[2*k2][2],   sc[2*k2][3],   pah[k2][1], pal[k2][1]);
            split2(sc[2*k2+1][0], sc[2*k2+1][1], pah[k2][2], pal[k2][2]);
            split2(sc[2*k2+1][2], sc[2*k2+1][3], pah[k2][3], pal[k2][3]);
        }

        // all warps done reading K smem -> start K_{kt+1}
        __syncthreads();
        if (kt < ktmax) {
            const size_t ko = koff0 + (size_t)(kt+1)*64*Dv;
            #pragma unroll
            for (int u = 0; u < 4; u++) {
                cp16(sb + KH +         drk + u*16, Kh + ko + u*8);
                cp16(sb + KH + KTILE + drk + u*16, Kl + ko + u*8);
            }
        }
        cp_commit();          // unconditional: keeps group numbering exact
        cp_wait<1>();         // V_kt ready
        __syncthreads();

        // ---- ctx += P @ V  (V via ldmatrix.trans) ----
        #pragma unroll
        for (int k2 = 0; k2 < 4; k2++) {
            #pragma unroll
            for (int p = 0; p < 8; p++) {
                const uint32_t vaddr = sb + VH +
                    (uint32_t)(((k2*16 + (lane & 15))*SP + p*16 + (lane >> 4)*8) * 2);
                uint32_t vh[4], vl[4];
                ldsm4t(vaddr,         vh);
                ldsm4t(vaddr + KTILE, vl);
                uint32_t bh0[2] = {vh[0], vh[1]}, bh1[2] = {vh[2], vh[3]};
                uint32_t bl0[2] = {vl[0], vl[1]}, bl1[2] = {vl[2], vl[3]};
                mma16816(ctxa[2*p],   pah[k2], bh0);
                mma16816(ctxa[2*p],   pal[k2], bh0);
                mma16816(ctxa[2*p],   pah[k2], bl0);
                mma16816(ctxa[2*p+1], pah[k2], bh1);
                mma16816(ctxa[2*p+1], pal[k2], bh1);
                mma16816(ctxa[2*p+1], pah[k2], bl1);
            }
        }
    }

    // epilogue: ctx/l -> bf16 hi/lo planes
    const float i0 = 1.0f / l0, i1 = 1.0f / l1;
    const size_t r0g = (size_t)(b*Sv + q0 + warp*16 + (lane >> 2));
    const size_t r1g = r0g + 8;
    #pragma unroll
    for (int nt = 0; nt < 16; nt++) {
        const size_t col = hoff + nt*8 + (lane & 3)*2;
        uint32_t h0, l0u, h1, l1u;
        split2(ctxa[nt][0]*i0, ctxa[nt][1]*i0, h0, l0u);
        split2(ctxa[nt][2]*i1, ctxa[nt][3]*i1, h1, l1u);
        *(uint32_t*)(ch + r0g*Dv + col) = h0;
        *(uint32_t*)(cl + r0g*Dv + col) = l0u;
        *(uint32_t*)(ch + r1g*Dv + col) = h1;
        *(uint32_t*)(cl + r1g*Dv + col) = l1u;
    }
}

// ---------------------------------------------------------------------------
extern "C" void kernel_launch(void* const* d_in, const int* in_sizes, int n_in,
                              void* d_out, int out_size)
{
    const float* x  = (const float*)d_in[0];
    const float* fc = (const float*)d_in[1];
    const float* fs = (const float*)d_in[2];
    // d_in[3] = mask (unused: -1e9 mask == strict causal in f32)
    const float* Wq = (const float*)d_in[4];
    const float* Wk = (const float*)d_in[5];
    const float* Wv = (const float*)d_in[6];
    const float* Wo = (const float*)d_in[7];

    float* out  = (float*)d_out;
    float* outK = out  + (size_t)Mv*Dv;
    float* outV = outK + (size_t)Mv*Dv;

    __nv_bfloat16 *xh, *xl, *wh, *wl, *qh, *ql, *kh, *kl, *vh, *vl, *ch, *cl;
    cudaGetSymbolAddress((void**)&xh, g_xh);
    cudaGetSymbolAddress((void**)&xl, g_xl);
    cudaGetSymbolAddress((void**)&wh, g_wh);
    cudaGetSymbolAddress((void**)&wl, g_wl);
    cudaGetSymbolAddress((void**)&qh, g_qh);
    cudaGetSymbolAddress((void**)&ql, g_ql);
    cudaGetSymbolAddress((void**)&kh, g_kh);
    cudaGetSymbolAddress((void**)&kl, g_kl);
    cudaGetSymbolAddress((void**)&vh, g_vh);
    cudaGetSymbolAddress((void**)&vl, g_vl);
    cudaGetSymbolAddress((void**)&ch, g_ch);
    cudaGetSymbolAddress((void**)&cl, g_cl);

    cudaFuncSetAttribute(gemm_qkv, cudaFuncAttributeMaxDynamicSharedMemorySize, GSM_TOTAL);
    cudaFuncSetAttribute(gemm_wo,  cudaFuncAttributeMaxDynamicSharedMemorySize, GSM_TOTAL);
    cudaFuncSetAttribute(attn_mma, cudaFuncAttributeMaxDynamicSharedMemorySize, ASM_TOT);

    const size_t WN = (size_t)Dv*Dv;     // 4M elems per weight

    split_x<<<(Mv*Dv/8 + 255)/256, 256>>>(x, xh, xl, Mv*Dv/8);
    split_w4<<<(int)(4*WN/8/256), 256>>>(Wq, Wk, Wv, Wo, wh, wl);

    dim3 ggrid(Dv/128, Mv/128, 3);   // (16, 32, 3)
    gemm_qkv<<<ggrid, GTHREADS, GSM_TOTAL>>>(xh, xl, wh, wl, fc, fs, outK, outV,
                                             qh, ql, kh, kl, vh, vl);

    attn_mma<<<dim3(Sv/128, Hv, Bv), 256, ASM_TOT>>>(qh, ql, kh, kl, vh, vl, ch, cl);

    gemm_wo<<<dim3(Dv/128, Mv/128), GTHREADS, GSM_TOTAL>>>(ch, cl, wh + 3*WN, wl + 3*WN, out);
}